// round 1
// baseline (speedup 1.0000x reference)
#include <cuda_runtime.h>
#include <math.h>

#define BB 256      // batch
#define SS 512      // seq len
#define IN_DIM 32
#define HH 256      // hidden
#define G3 768      // 3*H
#define NSTATE 4
#define DD 32
#define PRED 96

#define REC_GRID 128   // CTAs in recurrence kernel (1 per SM, co-resident)

// ---------------- scratch (device globals; no cudaMalloc allowed) ------------
__device__ float g_xT[(size_t)SS * IN_DIM * BB];        // [t][i][b]   16.8 MB
__device__ float g_xp[(size_t)SS * G3 * BB];            // [t][g][b]  402 MB
__device__ float g_h1[(size_t)SS * HH * BB];            // [t][c][b]  134 MB
__device__ float g_hbuf[2][HH * BB];                    // ping-pong h  512 KB
__device__ float g_s[BB * (NSTATE * DD)];               // proj output
__device__ unsigned g_bar;                              // grid barrier counter

// ---------------- pack x: [b][t][i] -> [t][i][b] ----------------------------
__global__ void pack_x_kernel(const float* __restrict__ x) {
    int t = blockIdx.x;
    __shared__ float sm[IN_DIM][BB];
    int b = threadIdx.x;
    const float* xp = x + ((size_t)b * SS + t) * IN_DIM;
#pragma unroll
    for (int i = 0; i < IN_DIM; i++) sm[i][b] = xp[i];
    __syncthreads();
    for (int idx = threadIdx.x; idx < IN_DIM * BB; idx += blockDim.x) {
        int i = idx / BB, bb = idx % BB;
        g_xT[((size_t)t * IN_DIM + i) * BB + bb] = sm[i][bb];
    }
}

// ---------------- GEMM: out[t][g][b] = sum_k A[t][k][b]*W[g][k] + bias[g] ---
// A is g_xT (K=IN_DIM) or g_h1 (K=HH), out is g_xp. 64 g's per CTA.
// 256 threads = 4 g-groups (16 g each) x 64 b-groups (4 b each).
template <int K>
__global__ __launch_bounds__(256, 2) void gemm_kernel(
    const float* __restrict__ W, const float* __restrict__ bias) {
    const float* A = (K == IN_DIM) ? g_xT : g_h1;
    int t = blockIdx.y;
    int g0 = blockIdx.x * 64;

    __shared__ float As[32 * BB];      // [kk][b]
    __shared__ float Wt[32 * 68];      // [kk][g], padded stride 68

    int tid = threadIdx.x;
    int tg = tid >> 6;                 // 0..3
    int tb = tid & 63;
    int b0 = tb * 4;

    float acc[4][16];
#pragma unroll
    for (int i = 0; i < 4; i++)
#pragma unroll
        for (int j = 0; j < 16; j++) acc[i][j] = 0.f;

    for (int kc = 0; kc < K; kc += 32) {
        // stage A chunk: 32 x 256 (coalesced)
#pragma unroll 4
        for (int i = tid; i < 32 * BB; i += 256) {
            int kk = i >> 8, b = i & 255;
            As[i] = A[((size_t)t * K + kc + kk) * BB + b];
        }
        // stage W chunk: [g][kk] -> Wt[kk][g] (coalesced reads over kk)
#pragma unroll 4
        for (int i = tid; i < 64 * 32; i += 256) {
            int g = i >> 5, kk = i & 31;
            Wt[kk * 68 + g] = W[(size_t)(g0 + g) * K + kc + kk];
        }
        __syncthreads();
#pragma unroll
        for (int kk = 0; kk < 32; kk++) {
            float4 av = *(const float4*)&As[kk * BB + b0];
            float aq[4] = {av.x, av.y, av.z, av.w};
#pragma unroll
            for (int j = 0; j < 4; j++) {
                float4 wv = *(const float4*)&Wt[kk * 68 + tg * 16 + j * 4];
                float wq[4] = {wv.x, wv.y, wv.z, wv.w};
#pragma unroll
                for (int bi = 0; bi < 4; bi++)
#pragma unroll
                    for (int q = 0; q < 4; q++)
                        acc[bi][j * 4 + q] += aq[bi] * wq[q];
            }
        }
        __syncthreads();
    }
#pragma unroll
    for (int j = 0; j < 16; j++) {
        int g = g0 + tg * 16 + j;
        float bv = bias[g];
        float4 o = make_float4(acc[0][j] + bv, acc[1][j] + bv,
                               acc[2][j] + bv, acc[3][j] + bv);
        *(float4*)&g_xp[((size_t)t * G3 + g) * BB + b0] = o;
    }
}

// ---------------- init for a recurrence launch -------------------------------
__global__ void init_kernel() {
    int i = blockIdx.x * blockDim.x + threadIdx.x;
    if (i == 0) g_bar = 0u;
    if (i < HH * BB) { g_hbuf[0][i] = 0.f; g_hbuf[1][i] = 0.f; }
}

__device__ __forceinline__ float sigmoidf_(float v) {
    return 1.f / (1.f + __expf(-v));
}

// ---------------- persistent GRU recurrence ---------------------------------
// 128 CTAs, each owns 2 hidden cols (6 gate rows of W_hh in SMEM).
// Threads: ks = tid>>6 (K-split of 4), tt = tid&63 (4 batch each).
template <int STORE_HIST>
__global__ __launch_bounds__(256, 1) void rec_kernel(
    const float* __restrict__ Whh, const float* __restrict__ bhh) {
    __shared__ float Ws[6 * HH];
    __shared__ float red[6 * 4 * BB];
    __shared__ float bh[6];

    int tid = threadIdx.x;
    int c0 = blockIdx.x * 2;

    for (int i = tid; i < 6 * HH; i += 256) {
        int slot = i >> 8, c = i & 255;
        int gate = slot >> 1, jj = slot & 1;
        Ws[slot * HH + c] = Whh[(size_t)(gate * HH + c0 + jj) * HH + c];
    }
    if (tid < 6) {
        int gate = tid >> 1, jj = tid & 1;
        bh[tid] = bhh[gate * HH + c0 + jj];
    }
    __syncthreads();

    int ks = tid >> 6;
    int tt = tid & 63;
    int b0 = tt * 4;
    int cbase = ks * 64;
    unsigned nblk = gridDim.x;

    for (int s = 0; s < SS; s++) {
        const float* hin = g_hbuf[s & 1];
        float* hout = g_hbuf[(s + 1) & 1];

        float a[6][4];
#pragma unroll
        for (int sl = 0; sl < 6; sl++) {
            a[sl][0] = 0.f; a[sl][1] = 0.f; a[sl][2] = 0.f; a[sl][3] = 0.f;
        }
#pragma unroll 4
        for (int cc = 0; cc < 64; cc++) {
            int c = cbase + cc;
            float4 hv = __ldcg((const float4*)&hin[c * BB + b0]);
#pragma unroll
            for (int sl = 0; sl < 6; sl++) {
                float w = Ws[sl * HH + c];
                a[sl][0] += w * hv.x; a[sl][1] += w * hv.y;
                a[sl][2] += w * hv.z; a[sl][3] += w * hv.w;
            }
        }
#pragma unroll
        for (int sl = 0; sl < 6; sl++) {
            *(float4*)&red[(sl * 4 + ks) * BB + b0] =
                make_float4(a[sl][0], a[sl][1], a[sl][2], a[sl][3]);
        }
        __syncthreads();

        // phase B: one batch element per thread
        {
            int b = tid;
            float P[6];
#pragma unroll
            for (int sl = 0; sl < 6; sl++) {
                P[sl] = red[(sl * 4 + 0) * BB + b] + red[(sl * 4 + 1) * BB + b] +
                        red[(sl * 4 + 2) * BB + b] + red[(sl * 4 + 3) * BB + b] +
                        bh[sl];
            }
            const float* xps = g_xp + (size_t)s * G3 * BB;
#pragma unroll
            for (int jj = 0; jj < 2; jj++) {
                int c = c0 + jj;
                float xr = xps[(0 * HH + c) * BB + b];
                float xz = xps[(1 * HH + c) * BB + b];
                float xn = xps[(2 * HH + c) * BB + b];
                float r = sigmoidf_(xr + P[0 + jj]);
                float z = sigmoidf_(xz + P[2 + jj]);
                float n = tanhf(xn + r * P[4 + jj]);
                float hold = __ldcg(&hin[c * BB + b]);
                float hnew = n + z * (hold - n);
                hout[c * BB + b] = hnew;
                if (STORE_HIST)
                    g_h1[((size_t)s * HH + c) * BB + b] = hnew;
            }
        }

        // grid barrier (all 128 CTAs co-resident)
        __threadfence();
        __syncthreads();
        if (tid == 0) {
            atomicAdd(&g_bar, 1u);
            unsigned target = nblk * (unsigned)(s + 1);
            while (atomicAdd(&g_bar, 0u) < target) {}
        }
        __syncthreads();
    }
}

// ---------------- projection: s[b][j] = final_h[b] . Wp[j] + bp[j] ----------
__global__ void proj_kernel(const float* __restrict__ Wp,
                            const float* __restrict__ bp) {
    int b = blockIdx.x;
    int j = threadIdx.x;  // 128
    const float* hf = g_hbuf[0];  // h after 512 steps lands in buffer 0
    float acc = bp[j];
#pragma unroll 8
    for (int c = 0; c < HH; c++)
        acc += hf[c * BB + b] * Wp[(size_t)j * HH + c];
    g_s[b * (NSTATE * DD) + j] = acc;
}

// ---------------- exponential-smoothing head --------------------------------
__global__ void es_kernel(const float* __restrict__ C,
                          const float* __restrict__ rl,
                          const float* __restrict__ rt,
                          const float* __restrict__ rg,
                          const float* __restrict__ om,
                          float* __restrict__ out) {
    int gid = blockIdx.x * blockDim.x + threadIdx.x;
    if (gid >= BB * DD) return;
    int b = gid / DD, d = gid % DD;
    float a_l = sigmoidf_(rl[d]) * 0.15f + 0.85f;
    float a_t = sigmoidf_(rt[d]) * 0.25f + 0.7f;
    float g = sigmoidf_(rg[d]) * 0.2f + 0.8f;
    float co = cosf(om[d]), sn = sinf(om[d]);
    float r00 = g * co, r01 = -g * sn, r10 = g * sn, r11 = g * co;
    float C0 = C[d * NSTATE + 0], C1 = C[d * NSTATE + 1];
    float C2 = C[d * NSTATE + 2], C3 = C[d * NSTATE + 3];
    float s0 = g_s[b * 128 + d * 4 + 0];
    float s1 = g_s[b * 128 + d * 4 + 1];
    float s2 = g_s[b * 128 + d * 4 + 2];
    float s3 = g_s[b * 128 + d * 4 + 3];
    for (int p = 0; p < PRED; p++) {
        float n0 = s0 * a_l;
        float n1 = s1 * a_t;
        float n2 = s2 * r00 + s3 * r10;
        float n3 = s2 * r01 + s3 * r11;
        out[((size_t)b * PRED + p) * DD + d] = C0 * n0 + C1 * n1 + C2 * n2 + C3 * n3;
        s0 = n0; s1 = n1; s2 = n2; s3 = n3;
    }
}

// ---------------- launch ----------------------------------------------------
extern "C" void kernel_launch(void* const* d_in, const int* in_sizes, int n_in,
                              void* d_out, int out_size) {
    (void)in_sizes; (void)n_in; (void)out_size;
    const float* x      = (const float*)d_in[0];
    const float* W_ih0  = (const float*)d_in[1];
    const float* W_hh0  = (const float*)d_in[2];
    const float* b_ih0  = (const float*)d_in[3];
    const float* b_hh0  = (const float*)d_in[4];
    const float* W_ih1  = (const float*)d_in[5];
    const float* W_hh1  = (const float*)d_in[6];
    const float* b_ih1  = (const float*)d_in[7];
    const float* b_hh1  = (const float*)d_in[8];
    const float* W_proj = (const float*)d_in[9];
    const float* b_proj = (const float*)d_in[10];
    const float* C      = (const float*)d_in[11];
    const float* rl     = (const float*)d_in[12];
    const float* rt     = (const float*)d_in[13];
    const float* rg     = (const float*)d_in[14];
    const float* om     = (const float*)d_in[15];
    float* out = (float*)d_out;

    // layer 0
    pack_x_kernel<<<SS, 256>>>(x);
    gemm_kernel<IN_DIM><<<dim3(G3 / 64, SS), 256>>>(W_ih0, b_ih0);
    init_kernel<<<(HH * BB + 255) / 256, 256>>>();
    rec_kernel<1><<<REC_GRID, 256>>>(W_hh0, b_hh0);

    // layer 1
    gemm_kernel<HH><<<dim3(G3 / 64, SS), 256>>>(W_ih1, b_ih1);
    init_kernel<<<(HH * BB + 255) / 256, 256>>>();
    rec_kernel<0><<<REC_GRID, 256>>>(W_hh1, b_hh1);

    // head
    proj_kernel<<<BB, 128>>>(W_proj, b_proj);
    es_kernel<<<(BB * DD + 255) / 256, 256>>>(C, rl, rt, rg, om, out);
}

// round 4
// speedup vs baseline: 1.7936x; 1.7936x over previous
#include <cuda_runtime.h>
#include <cuda_bf16.h>
#include <math.h>
#include <stdint.h>

#define BB 256      // batch
#define SS 512      // seq len
#define IN_DIM 32
#define HH 256      // hidden
#define G3 768      // 3*H
#define DD 32
#define PRED 96

#define REC_CTAS 128   // 16 c-tiles x 8 b-tiles, all co-resident (<=148 SMs)

// ---------------- scratch (device globals; no cudaMalloc allowed) ------------
__device__ float g_xT[(size_t)SS * IN_DIM * BB];        // [t][i][b]
__device__ float g_xp[(size_t)SS * G3 * BB];            // [t][g][b]
__device__ float g_hbuf[2][HH * BB];                    // final h (f32, [c][b])
__device__ float g_s[BB * 128];                         // proj output
__device__ unsigned g_bar;                              // grid barrier counter

// bf16 hi/lo state + history + split weights
__device__ __nv_bfloat16 g_hhh[2][BB * HH];             // step state [b][c] hi
__device__ __nv_bfloat16 g_hhl[2][BB * HH];             // step state [b][c] lo
__device__ __nv_bfloat16 g_h1h[(size_t)SS * BB * HH];   // layer0 hist [t][b][c]
__device__ __nv_bfloat16 g_h1l[(size_t)SS * BB * HH];
__device__ __nv_bfloat16 g_Whi[G3 * HH];                // W_ih1 split hi
__device__ __nv_bfloat16 g_Wlo[G3 * HH];                // W_ih1 split lo

__device__ __forceinline__ float sigmoidf_(float v) {
    return 1.f / (1.f + __expf(-v));
}

// mma.sync m16n8k16 bf16 (arch-portable PTX, no 103a feature needed)
__device__ __forceinline__ void mma16816(float* d,
                                         uint32_t a0, uint32_t a1,
                                         uint32_t a2, uint32_t a3,
                                         uint32_t b0, uint32_t b1) {
    asm("mma.sync.aligned.m16n8k16.row.col.f32.bf16.bf16.f32 "
        "{%0,%1,%2,%3}, {%4,%5,%6,%7}, {%8,%9}, {%0,%1,%2,%3};"
        : "+f"(d[0]), "+f"(d[1]), "+f"(d[2]), "+f"(d[3])
        : "r"(a0), "r"(a1), "r"(a2), "r"(a3), "r"(b0), "r"(b1));
}

// ---------------- pack x: [b][t][i] -> [t][i][b] ----------------------------
__global__ void pack_x_kernel(const float* __restrict__ x) {
    int t = blockIdx.x;
    __shared__ float sm[IN_DIM][BB];
    int b = threadIdx.x;
    const float* xp = x + ((size_t)b * SS + t) * IN_DIM;
#pragma unroll
    for (int i = 0; i < IN_DIM; i++) sm[i][b] = xp[i];
    __syncthreads();
    for (int idx = threadIdx.x; idx < IN_DIM * BB; idx += blockDim.x) {
        int i = idx / BB, bb = idx % BB;
        g_xT[((size_t)t * IN_DIM + i) * BB + bb] = sm[i][bb];
    }
}

// ---------------- FFMA GEMM for layer-0 xp (K=32, small) ---------------------
__global__ __launch_bounds__(256, 2) void gemm32_kernel(
    const float* __restrict__ W, const float* __restrict__ bias) {
    const int K = IN_DIM;
    int t = blockIdx.y;
    int g0 = blockIdx.x * 64;

    __shared__ float As[32 * BB];
    __shared__ float Wt[32 * 68];

    int tid = threadIdx.x;
    int tg = tid >> 6;
    int tb = tid & 63;
    int b0 = tb * 4;

    float acc[4][16];
#pragma unroll
    for (int i = 0; i < 4; i++)
#pragma unroll
        for (int j = 0; j < 16; j++) acc[i][j] = 0.f;

#pragma unroll 4
    for (int i = tid; i < 32 * BB; i += 256) {
        int kk = i >> 8, b = i & 255;
        As[i] = g_xT[((size_t)t * K + kk) * BB + b];
    }
#pragma unroll 4
    for (int i = tid; i < 64 * 32; i += 256) {
        int g = i >> 5, kk = i & 31;
        Wt[kk * 68 + g] = W[(size_t)(g0 + g) * K + kk];
    }
    __syncthreads();
#pragma unroll
    for (int kk = 0; kk < 32; kk++) {
        float4 av = *(const float4*)&As[kk * BB + b0];
        float aq[4] = {av.x, av.y, av.z, av.w};
#pragma unroll
        for (int j = 0; j < 4; j++) {
            float4 wv = *(const float4*)&Wt[kk * 68 + tg * 16 + j * 4];
            float wq[4] = {wv.x, wv.y, wv.z, wv.w};
#pragma unroll
            for (int bi = 0; bi < 4; bi++)
#pragma unroll
                for (int q = 0; q < 4; q++)
                    acc[bi][j * 4 + q] += aq[bi] * wq[q];
        }
    }
#pragma unroll
    for (int j = 0; j < 16; j++) {
        int g = g0 + tg * 16 + j;
        float bv = bias[g];
        float4 o = make_float4(acc[0][j] + bv, acc[1][j] + bv,
                               acc[2][j] + bv, acc[3][j] + bv);
        *(float4*)&g_xp[((size_t)t * G3 + g) * BB + b0] = o;
    }
}

// ---------------- W split: fp32 -> bf16 hi/lo (for xp1 mma GEMM) -------------
__global__ void w_split_kernel(const float* __restrict__ W) {
    int i = blockIdx.x * 256 + threadIdx.x;
    if (i < G3 * HH) {
        float v = W[i];
        __nv_bfloat16 hi = __float2bfloat16(v);
        g_Whi[i] = hi;
        g_Wlo[i] = __float2bfloat16(v - __bfloat162float(hi));
    }
}

// ---------------- init: zero step-state buffer 0 + barrier -------------------
__global__ void init_kernel() {
    int i = blockIdx.x * blockDim.x + threadIdx.x;
    if (i == 0) g_bar = 0u;
    if (i < HH * BB) {
        g_hhh[0][i] = __float2bfloat16(0.f);
        g_hhl[0][i] = __float2bfloat16(0.f);
    }
}

// ---------------- persistent MMA GRU recurrence ------------------------------
// 128 CTAs = 16 c-tiles(16c) x 8 b-tiles(32b), 128 threads (4 warps).
// A (smem, persistent): 48 rows = {r,z,n} x 16c of W_hh, bf16 hi+lo, K=256.
// B (smem, per step): h state bf16 hi+lo, [32 b][256 c], staged via __ldcg.
// K' = 768 as three passes: Whi*hhi + Wlo*hhi + Whi*hlo  (fp32-class accuracy).
// Each thread's 3 m-frags carry r/z/n preacts for the SAME (c,b): gates are
// thread-local; h_old lives in registers. ONE grid barrier per step.
#define REC_SMEM (48 * 264 * 2 * 2 + 32 * 264 * 2 * 2 + 48 * 4)

template <int STORE_HIST>
__global__ __launch_bounds__(128, 1) void rec_mma_kernel(
    const float* __restrict__ Whh, const float* __restrict__ bhh) {
    extern __shared__ char smraw[];
    __nv_bfloat16* Whi = (__nv_bfloat16*)smraw;          // [48][264]
    __nv_bfloat16* Wlo = Whi + 48 * 264;
    __nv_bfloat16* Bh  = Wlo + 48 * 264;                 // [32][264]
    __nv_bfloat16* Bl  = Bh + 32 * 264;
    float* bh = (float*)(Bl + 32 * 264);                 // [48]

    int tid = threadIdx.x;
    int lane = tid & 31, wid = tid >> 5;
    int gid = lane >> 2, tig = lane & 3;
    int ct = blockIdx.x >> 3, bt = blockIdx.x & 7;
    int c0 = ct * 16, b0 = bt * 32;

    // load + split the 48 W_hh rows for this c-tile
    for (int i = tid; i < 48 * 256; i += 128) {
        int r = i >> 8, k = i & 255;
        int grow = (r >> 4) * HH + c0 + (r & 15);
        float f = Whh[(size_t)grow * HH + k];
        __nv_bfloat16 hi = __float2bfloat16(f);
        Whi[r * 264 + k] = hi;
        Wlo[r * 264 + k] = __float2bfloat16(f - __bfloat162float(hi));
    }
    if (tid < 48) {
        int grow = (tid >> 4) * HH + c0 + (tid & 15);
        bh[tid] = bhh[grow];
    }
    __syncthreads();

    int b  = b0 + wid * 8 + tig * 2;   // this thread's batch pair base
    int cA = c0 + gid;                 // c for frag rows gid
    int cB = cA + 8;                   // c for frag rows gid+8
    float hold[4] = {0.f, 0.f, 0.f, 0.f};
    unsigned nblk = gridDim.x;

    for (int s = 0; s < SS; s++) {
        // prefetch xp for the gate phase (latency hidden under stage+mma)
        const float* xps = g_xp + (size_t)s * G3 * BB;
        float2 px[6];
#pragma unroll
        for (int g = 0; g < 3; g++) {
            px[g * 2 + 0] = *(const float2*)&xps[(g * HH + cA) * BB + b];
            px[g * 2 + 1] = *(const float2*)&xps[(g * HH + cB) * BB + b];
        }

        // stage h state for this b-tile (L2-only loads: L1 may be stale)
        const uint4* srcH = (const uint4*)(g_hhh[s & 1] + (size_t)b0 * HH);
        const uint4* srcL = (const uint4*)(g_hhl[s & 1] + (size_t)b0 * HH);
#pragma unroll
        for (int i2 = 0; i2 < 8; i2++) {
            int i = tid + i2 * 128;
            int row = i >> 5, seg = i & 31;
            uint4 vh = __ldcg(srcH + row * 32 + seg);
            uint4 vl = __ldcg(srcL + row * 32 + seg);
            *(uint4*)&Bh[row * 264 + seg * 8] = vh;
            *(uint4*)&Bl[row * 264 + seg * 8] = vl;
        }
        __syncthreads();

        float acc[3][4];
#pragma unroll
        for (int mf = 0; mf < 3; mf++) {
            acc[mf][0] = 0.f; acc[mf][1] = 0.f;
            acc[mf][2] = 0.f; acc[mf][3] = 0.f;
        }

        int brow = (wid * 8 + gid) * 264;
#pragma unroll
        for (int p = 0; p < 3; p++) {
            const __nv_bfloat16* Am = (p == 1) ? Wlo : Whi;
            const __nv_bfloat16* Bm = (p == 2) ? Bl : Bh;
#pragma unroll
            for (int ks = 0; ks < 16; ks++) {
                int k0 = ks * 16 + tig * 2;
                uint32_t br0 = *(const uint32_t*)&Bm[brow + k0];
                uint32_t br1 = *(const uint32_t*)&Bm[brow + k0 + 8];
#pragma unroll
                for (int mf = 0; mf < 3; mf++) {
                    const __nv_bfloat16* ap = Am + (mf * 16 + gid) * 264 + k0;
                    uint32_t a0 = *(const uint32_t*)(ap);
                    uint32_t a1 = *(const uint32_t*)(ap + 8 * 264);
                    uint32_t a2 = *(const uint32_t*)(ap + 8);
                    uint32_t a3 = *(const uint32_t*)(ap + 8 * 264 + 8);
                    mma16816(acc[mf], a0, a1, a2, a3, br0, br1);
                }
            }
        }

        // gate phase: thread-local (same (c,b) across the 3 gate frags)
        int nb = (s + 1) & 1;
        __nv_bfloat16* dstH = g_hhh[nb];
        __nv_bfloat16* dstL = g_hhl[nb];
        float hnew[4];
#pragma unroll
        for (int jj = 0; jj < 4; jj++) {
            int cl = (jj < 2) ? gid : gid + 8;
            int half = jj >> 1;
            float xr = (jj & 1) ? px[0 + half].y : px[0 + half].x;
            float xz = (jj & 1) ? px[2 + half].y : px[2 + half].x;
            float xn = (jj & 1) ? px[4 + half].y : px[4 + half].x;
            float r = sigmoidf_(xr + acc[0][jj] + bh[cl]);
            float z = sigmoidf_(xz + acc[1][jj] + bh[16 + cl]);
            float n = tanhf(xn + r * (acc[2][jj] + bh[32 + cl]));
            float hv = n + z * (hold[jj] - n);
            hold[jj] = hv;
            hnew[jj] = hv;
        }
#pragma unroll
        for (int jj = 0; jj < 4; jj++) {
            int bb2 = b + (jj & 1);
            int cc = (jj < 2) ? cA : cB;
            __nv_bfloat16 hi = __float2bfloat16(hnew[jj]);
            __nv_bfloat16 lo = __float2bfloat16(hnew[jj] - __bfloat162float(hi));
            dstH[bb2 * HH + cc] = hi;
            dstL[bb2 * HH + cc] = lo;
            if (STORE_HIST) {
                size_t o = ((size_t)s * BB + bb2) * HH + cc;
                g_h1h[o] = hi;
                g_h1l[o] = lo;
            }
        }
        if (s == SS - 1) {
            *(float2*)&g_hbuf[0][cA * BB + b] = make_float2(hnew[0], hnew[1]);
            *(float2*)&g_hbuf[0][cB * BB + b] = make_float2(hnew[2], hnew[3]);
        }

        // grid barrier (128 co-resident CTAs)
        __threadfence();
        __syncthreads();
        if (tid == 0) {
            atomicAdd(&g_bar, 1u);
            unsigned target = nblk * (unsigned)(s + 1);
            while (atomicAdd(&g_bar, 0u) < target) {}
        }
        __syncthreads();
    }
}

// ---------------- mma.sync bf16x3 GEMM: xp1[t][g][b] -------------------------
// CTA tile 128g x 128b, K'=768 (three 256-k regions) in 12 chunks of 64.
// 8 warps: 2m x 4n, warp tile 64x32 (4 m-frags x 4 n-frags).
#define GEMM_SMEM (2 * 128 * 72 * 2)

__global__ __launch_bounds__(256, 1) void gemm_mma_kernel(
    const float* __restrict__ bias) {
    extern __shared__ char smraw[];
    __nv_bfloat16* As = (__nv_bfloat16*)smraw;   // [128][72]
    __nv_bfloat16* Bs = As + 128 * 72;
    int tid = threadIdx.x, lane = tid & 31, wid = tid >> 5;
    int gid = lane >> 2, tig = lane & 3;
    int bx = blockIdx.x;
    int m = bx % 6, bt = (bx / 6) & 1, t = bx / 12;
    int g0 = m * 128, bg0 = bt * 128;
    int wm = wid & 1, wn = wid >> 1;

    float acc[4][4][4];
#pragma unroll
    for (int i = 0; i < 4; i++)
#pragma unroll
        for (int j = 0; j < 4; j++) {
            acc[i][j][0] = 0.f; acc[i][j][1] = 0.f;
            acc[i][j][2] = 0.f; acc[i][j][3] = 0.f;
        }

    uint4 pa[4], pb[4];
    auto fetch = [&](int q) {
        int r = q >> 2, kc = (q & 3) * 64;
        const __nv_bfloat16* Asrc = (r == 1) ? g_Wlo : g_Whi;
        const __nv_bfloat16* Bsrc =
            ((r == 2) ? g_h1l : g_h1h) + (size_t)t * BB * HH;
#pragma unroll
        for (int i = 0; i < 4; i++) {
            int idx = tid + i * 256;
            int row = idx >> 3, seg = idx & 7;
            pa[i] = *(const uint4*)&Asrc[(size_t)(g0 + row) * HH + kc + seg * 8];
            pb[i] = *(const uint4*)&Bsrc[(size_t)(bg0 + row) * HH + kc + seg * 8];
        }
    };
    fetch(0);
    for (int q = 0; q < 12; q++) {
#pragma unroll
        for (int i = 0; i < 4; i++) {
            int idx = tid + i * 256;
            int row = idx >> 3, seg = idx & 7;
            *(uint4*)&As[row * 72 + seg * 8] = pa[i];
            *(uint4*)&Bs[row * 72 + seg * 8] = pb[i];
        }
        __syncthreads();
        if (q < 11) fetch(q + 1);
#pragma unroll
        for (int ks = 0; ks < 4; ks++) {
            int k0 = ks * 16 + tig * 2;
            uint32_t brg[4][2];
#pragma unroll
            for (int nf = 0; nf < 4; nf++) {
                int row = (wn * 32 + nf * 8 + gid) * 72;
                brg[nf][0] = *(const uint32_t*)&Bs[row + k0];
                brg[nf][1] = *(const uint32_t*)&Bs[row + k0 + 8];
            }
#pragma unroll
            for (int mf = 0; mf < 4; mf++) {
                const __nv_bfloat16* ap = As + (wm * 64 + mf * 16 + gid) * 72 + k0;
                uint32_t a0 = *(const uint32_t*)(ap);
                uint32_t a1 = *(const uint32_t*)(ap + 8 * 72);
                uint32_t a2 = *(const uint32_t*)(ap + 8);
                uint32_t a3 = *(const uint32_t*)(ap + 8 * 72 + 8);
#pragma unroll
                for (int nf = 0; nf < 4; nf++)
                    mma16816(acc[mf][nf], a0, a1, a2, a3,
                             brg[nf][0], brg[nf][1]);
            }
        }
        __syncthreads();
    }
    // epilogue
#pragma unroll
    for (int mf = 0; mf < 4; mf++) {
        int g = g0 + wm * 64 + mf * 16 + gid;
        float bv0 = bias[g], bv1 = bias[g + 8];
        float* o0 = g_xp + ((size_t)t * G3 + g) * BB;
        float* o1 = o0 + 8 * BB;
#pragma unroll
        for (int nf = 0; nf < 4; nf++) {
            int bb2 = bg0 + wn * 32 + nf * 8 + tig * 2;
            *(float2*)&o0[bb2] =
                make_float2(acc[mf][nf][0] + bv0, acc[mf][nf][1] + bv0);
            *(float2*)&o1[bb2] =
                make_float2(acc[mf][nf][2] + bv1, acc[mf][nf][3] + bv1);
        }
    }
}

// ---------------- projection -------------------------------------------------
__global__ void proj_kernel(const float* __restrict__ Wp,
                            const float* __restrict__ bp) {
    int b = blockIdx.x;
    int j = threadIdx.x;  // 128
    const float* hf = g_hbuf[0];
    float acc = bp[j];
#pragma unroll 8
    for (int c = 0; c < HH; c++)
        acc += hf[c * BB + b] * Wp[(size_t)j * HH + c];
    g_s[b * 128 + j] = acc;
}

// ---------------- exponential-smoothing head ---------------------------------
__global__ void es_kernel(const float* __restrict__ C,
                          const float* __restrict__ rl,
                          const float* __restrict__ rt,
                          const float* __restrict__ rg,
                          const float* __restrict__ om,
                          float* __restrict__ out) {
    int gid = blockIdx.x * blockDim.x + threadIdx.x;
    if (gid >= BB * DD) return;
    int b = gid / DD, d = gid % DD;
    float a_l = sigmoidf_(rl[d]) * 0.15f + 0.85f;
    float a_t = sigmoidf_(rt[d]) * 0.25f + 0.7f;
    float g = sigmoidf_(rg[d]) * 0.2f + 0.8f;
    float co = cosf(om[d]), sn = sinf(om[d]);
    float r00 = g * co, r01 = -g * sn, r10 = g * sn, r11 = g * co;
    float C0 = C[d * 4 + 0], C1 = C[d * 4 + 1];
    float C2 = C[d * 4 + 2], C3 = C[d * 4 + 3];
    float s0 = g_s[b * 128 + d * 4 + 0];
    float s1 = g_s[b * 128 + d * 4 + 1];
    float s2 = g_s[b * 128 + d * 4 + 2];
    float s3 = g_s[b * 128 + d * 4 + 3];
    for (int p = 0; p < PRED; p++) {
        float n0 = s0 * a_l;
        float n1 = s1 * a_t;
        float n2 = s2 * r00 + s3 * r10;
        float n3 = s2 * r01 + s3 * r11;
        out[((size_t)b * PRED + p) * DD + d] =
            C0 * n0 + C1 * n1 + C2 * n2 + C3 * n3;
        s0 = n0; s1 = n1; s2 = n2; s3 = n3;
    }
}

// ---------------- launch ----------------------------------------------------
extern "C" void kernel_launch(void* const* d_in, const int* in_sizes, int n_in,
                              void* d_out, int out_size) {
    (void)in_sizes; (void)n_in; (void)out_size;
    const float* x      = (const float*)d_in[0];
    const float* W_ih0  = (const float*)d_in[1];
    const float* W_hh0  = (const float*)d_in[2];
    const float* b_ih0  = (const float*)d_in[3];
    const float* b_hh0  = (const float*)d_in[4];
    const float* W_ih1  = (const float*)d_in[5];
    const float* W_hh1  = (const float*)d_in[6];
    const float* b_ih1  = (const float*)d_in[7];
    const float* b_hh1  = (const float*)d_in[8];
    const float* W_proj = (const float*)d_in[9];
    const float* b_proj = (const float*)d_in[10];
    const float* C      = (const float*)d_in[11];
    const float* rl     = (const float*)d_in[12];
    const float* rt     = (const float*)d_in[13];
    const float* rg     = (const float*)d_in[14];
    const float* om     = (const float*)d_in[15];
    float* out = (float*)d_out;

    cudaFuncSetAttribute(rec_mma_kernel<1>,
                         cudaFuncAttributeMaxDynamicSharedMemorySize, REC_SMEM);
    cudaFuncSetAttribute(rec_mma_kernel<0>,
                         cudaFuncAttributeMaxDynamicSharedMemorySize, REC_SMEM);
    cudaFuncSetAttribute(gemm_mma_kernel,
                         cudaFuncAttributeMaxDynamicSharedMemorySize, GEMM_SMEM);

    // layer 0
    pack_x_kernel<<<SS, 256>>>(x);
    w_split_kernel<<<(G3 * HH + 255) / 256, 256>>>(W_ih1);  // prep for xp1
    gemm32_kernel<<<dim3(G3 / 64, SS), 256>>>(W_ih0, b_ih0);
    init_kernel<<<(HH * BB + 255) / 256, 256>>>();
    rec_mma_kernel<1><<<REC_CTAS, 128, REC_SMEM>>>(W_hh0, b_hh0);

    // layer 1
    gemm_mma_kernel<<<SS * 12, 256, GEMM_SMEM>>>(b_ih1);
    init_kernel<<<(HH * BB + 255) / 256, 256>>>();
    rec_mma_kernel<0><<<REC_CTAS, 128, REC_SMEM>>>(W_hh1, b_hh1);

    // head
    proj_kernel<<<BB, 128>>>(W_proj, b_proj);
    es_kernel<<<(BB * DD + 255) / 256, 256>>>(C, rl, rt, rg, om, out);
}